// round 13
// baseline (speedup 1.0000x reference)
#include <cuda_runtime.h>
#include <cuda_bf16.h>
#include <cstdint>

#define BROWS 8192
#define NF 1024
#define KTOT 13312              // 13 terms x 1024 along fused K axis

#define NBA 128                 // A-builder blocks (64 rowblocks x 2 col-halves)
#define NBW 13                  // W-builder blocks (one per term)
#define NBUILD 142              // 128 + 13 + 1 bias
#define NGEMM 512

__device__ __align__(256) __nv_bfloat16 g_A[(size_t)BROWS * KTOT];  // [row][t*1024+k]
__device__ __align__(256) __nv_bfloat16 g_W[(size_t)NF * KTOT];     // [n][t*1024+k]
__device__ __align__(256) __nv_bfloat16 g_O[(size_t)BROWS * NF];    // bf16 chain / pre-RMS out
__device__ __align__(256) __nv_bfloat16 g_bias[NF];
__device__ __align__(256) float g_xs[(size_t)BROWS * NF];           // f32 tanh(x) scratch
__device__ int g_flagA[13 * 64];
__device__ int g_flagW[13];
__device__ int g_flagB;

__device__ __forceinline__ uint32_t smem_u32(const void* p) {
    uint32_t a;
    asm("{ .reg .u64 t; cvta.to.shared.u64 t, %1; cvt.u32.u64 %0, t; }" : "=r"(a) : "l"(p));
    return a;
}
__device__ __forceinline__ void cp16(uint32_t d, const void* s) {
    asm volatile("cp.async.cg.shared.global [%0], [%1], 16;" :: "r"(d), "l"(s) : "memory");
}
__device__ __forceinline__ void ldsm4(uint32_t* r, uint32_t a) {
    asm volatile("ldmatrix.sync.aligned.m8n8.x4.shared.b16 {%0,%1,%2,%3}, [%4];"
        : "=r"(r[0]), "=r"(r[1]), "=r"(r[2]), "=r"(r[3]) : "r"(a));
}
__device__ __forceinline__ void mma16816(float* c, const uint32_t* a, uint32_t b0, uint32_t b1) {
    asm volatile("mma.sync.aligned.m16n8k16.row.col.f32.bf16.bf16.f32 "
        "{%0,%1,%2,%3}, {%4,%5,%6,%7}, {%8,%9}, {%0,%1,%2,%3};"
        : "+f"(c[0]), "+f"(c[1]), "+f"(c[2]), "+f"(c[3])
        : "r"(a[0]), "r"(a[1]), "r"(a[2]), "r"(a[3]), "r"(b0), "r"(b1));
}
__device__ __forceinline__ uint32_t cvt2(float hi, float lo) {
    uint32_t d; asm("cvt.rn.bf16x2.f32 %0, %1, %2;" : "=r"(d) : "f"(hi), "f"(lo)); return d;
}
__device__ __forceinline__ uint32_t badd2(uint32_t a, uint32_t b) {
    uint32_t d; asm("add.rn.bf16x2 %0, %1, %2;" : "=r"(d) : "r"(a), "r"(b)); return d;
}
__device__ __forceinline__ uint32_t swz(uint32_t off) { return off ^ ((off >> 3) & 0x70); }
__device__ __forceinline__ void spinf(int* f, int target) {
    int v;
    while (true) {
        asm volatile("ld.acquire.gpu.b32 %0, [%1];" : "=r"(v) : "l"(f) : "memory");
        if (v >= target) break;
        __nanosleep(64);
    }
}

// ---- kernel A: zero flags (per-replay determinism) ----
__global__ void kan_zero() {
    int i = threadIdx.x;
    for (int j = i; j < 13 * 64; j += 256) g_flagA[j] = 0;
    if (i < 13) g_flagW[i] = 0;
    if (i == 0) g_flagB = 0;
}

// ---- GEMM chunk loader ----
#define STG_B 32768u            // A 128x64 (16KB) + W 128x64 (16KB)
#define SMEM_SZ (3 * 32768)
#define NCHUNK 208              // 13312/64; term t = chunk>>4

__device__ __forceinline__ void load_chunk(uint32_t sb, int g, int tid, int m0, int n0) {
    uint32_t stg = sb + (uint32_t)(g % 3) * STG_B;
    const __nv_bfloat16* Ab = g_A + (size_t)m0 * KTOT + g * 64;
    const __nv_bfloat16* Wb = g_W + (size_t)n0 * KTOT + g * 64;
#pragma unroll
    for (int k = 0; k < 8; k++) {
        int i = tid + k * 256;
        int half_ = i >> 10, j = i & 1023, r = j >> 3, s = j & 7;
        const __nv_bfloat16* src = (half_ ? Wb : Ab) + (size_t)r * KTOT + s * 8;
        cp16(stg + (half_ ? 16384u : 0u) + swz((uint32_t)(r * 128 + s * 16)), src);
    }
}

// ---- fused mega-kernel: builders + GEMM ----
__global__ __launch_bounds__(256, 2) void kan_gemm(const float* __restrict__ xin,
                                                   const float* __restrict__ bw,
                                                   const float* __restrict__ pw) {
    extern __shared__ char smem[];
    int bid = blockIdx.x, tid = threadIdx.x;

    if (bid < NBA) {
        // ===== A builder: rowblock rb (128 rows), column half ch (512 cols) =====
        int rb = bid >> 1, ch = bid & 1;
        const float* xp0 = xin + (size_t)(rb * 128) * NF + ch * 512;
        float* xsb = g_xs + (size_t)(rb * 128) * NF + ch * 512;
        __nv_bfloat16* ab = g_A + (size_t)(rb * 128) * KTOT + ch * 512;
        // pass 1: silu (term 0), xs scratch, T1 (term 1)
        for (int i = 0; i < 32; i++) {
            int u = i * 256 + tid, row = u >> 6, grp = u & 63;
            const float4* xp = reinterpret_cast<const float4*>(xp0 + (size_t)row * NF + grp * 8);
            float4 xa = xp[0], xb4 = xp[1];
            float xv[8] = {xa.x, xa.y, xa.z, xa.w, xb4.x, xb4.y, xb4.z, xb4.w};
            float a0[8], xsv[8];
#pragma unroll
            for (int e = 0; e < 8; e++) {
                float xf = __bfloat162float(__float2bfloat16(xv[e]));
                float ee = __bfloat162float(__float2bfloat16(expf(-xf)));
                float dd = __bfloat162float(__float2bfloat16(1.0f + ee));
                float s  = __bfloat162float(__float2bfloat16(1.0f / dd));
                a0[e] = xf * s;
                xsv[e] = tanhf(xv[e]);
            }
            __nv_bfloat16* d0 = ab + (size_t)row * KTOT + grp * 8;
            *reinterpret_cast<uint4*>(d0) =
                make_uint4(cvt2(a0[1], a0[0]), cvt2(a0[3], a0[2]), cvt2(a0[5], a0[4]), cvt2(a0[7], a0[6]));
            *reinterpret_cast<uint4*>(d0 + 1024) =
                make_uint4(cvt2(xsv[1], xsv[0]), cvt2(xsv[3], xsv[2]), cvt2(xsv[5], xsv[4]), cvt2(xsv[7], xsv[6]));
            float4* xd = reinterpret_cast<float4*>(xsb + (size_t)row * NF + grp * 8);
            xd[0] = make_float4(xsv[0], xsv[1], xsv[2], xsv[3]);
            xd[1] = make_float4(xsv[4], xsv[5], xsv[6], xsv[7]);
        }
        __syncthreads(); __threadfence();
        if (tid == 0) { atomicAdd(&g_flagA[rb], 1); atomicAdd(&g_flagA[64 + rb], 1); }
        // passes t=2..12: recompute recursion from xs (same-thread data, no sync needed)
        for (int t = 2; t <= 12; t++) {
            for (int i = 0; i < 32; i++) {
                int u = i * 256 + tid, row = u >> 6, grp = u & 63;
                const float4* xd = reinterpret_cast<const float4*>(xsb + (size_t)row * NF + grp * 8);
                float4 s0 = xd[0], s1 = xd[1];
                float xs8[8] = {s0.x, s0.y, s0.z, s0.w, s1.x, s1.y, s1.z, s1.w};
                float tv[8];
#pragma unroll
                for (int e = 0; e < 8; e++) {
                    float xs = xs8[e], Tp = 1.0f, Tc = xs;
                    for (int j = 2; j <= t; j++) { float Tn = 2.0f * xs * Tc - Tp; Tp = Tc; Tc = Tn; }
                    tv[e] = Tc;
                }
                *reinterpret_cast<uint4*>(ab + (size_t)row * KTOT + t * 1024 + grp * 8) =
                    make_uint4(cvt2(tv[1], tv[0]), cvt2(tv[3], tv[2]), cvt2(tv[5], tv[4]), cvt2(tv[7], tv[6]));
            }
            __syncthreads(); __threadfence();
            if (tid == 0) atomicAdd(&g_flagA[t * 64 + rb], 1);
        }
        return;
    }
    if (bid < NBA + NBW) {
        // ===== W builder: transpose term t to [n][t*1024+k] bf16 =====
        int t = bid - NBA;
        const float* src = (t == 0) ? bw : (pw + (size_t)t * NF * NF);
        float* tl = reinterpret_cast<float*>(smem);   // 32x33 tile
        int tx = tid & 31, ty = tid >> 5;
        for (int ti = 0; ti < 1024; ti++) {
            int n0 = (ti & 31) * 32, k0 = (ti >> 5) * 32;
#pragma unroll
            for (int r = 0; r < 4; r++)
                tl[(ty + r * 8) * 33 + tx] = src[(size_t)(k0 + ty + r * 8) * NF + n0 + tx];
            __syncthreads();
#pragma unroll
            for (int r = 0; r < 4; r++)
                g_W[(size_t)(n0 + ty + r * 8) * KTOT + t * 1024 + k0 + tx] = __float2bfloat16(tl[tx * 33 + ty + r * 8]);
            __syncthreads();
        }
        __threadfence();
        if (tid == 0) atomicAdd(&g_flagW[t], 1);
        return;
    }
    if (bid == NBA + NBW) {
        // ===== bias builder: bf16( f32 colsum of bf16(pw[0]) ) =====
        for (int c4 = 0; c4 < 4; c4++) {
            int col = tid + c4 * 256;
            float a = 0.0f;
            for (int k = 0; k < NF; k++)
                a += __bfloat162float(__float2bfloat16(pw[(size_t)k * NF + col]));
            g_bias[col] = __float2bfloat16(a);
        }
        __syncthreads(); __threadfence();
        if (tid == 0) atomicAdd(&g_flagB, 1);
        return;
    }

    // ===== GEMM (R11 core): 128x128 CTA tile, 8 warps @ 32x64, 2 CTAs/SM =====
    uint32_t sb = smem_u32(smem);
    int tile = bid - NBUILD;
    int wid = tid >> 5, lane = tid & 31;
    int m0 = (tile >> 3) * 128, n0 = (tile & 7) * 128;
    int rbm = tile >> 3;                      // flag rowblock
    int mw = wid >> 1, nw = wid & 1;          // 4x2 warp grid, warp tile 32x64
    uint32_t rowA0 = (uint32_t)((mw * 32 + (lane & 15)) * 128);
    uint32_t rowB0 = (uint32_t)((nw * 64 + (lane & 15)) * 128);
    uint32_t kbase = (uint32_t)((lane >> 4) * 16);

    float acc[2][8][4];
#pragma unroll
    for (int a = 0; a < 2; a++)
#pragma unroll
        for (int b = 0; b < 8; b++)
#pragma unroll
            for (int r = 0; r < 4; r++) acc[a][b][r] = 0.0f;

    uint32_t afr[2][2][4];
    uint32_t bfr[2][4][4];

    if (tid == 0) { spinf(&g_flagA[rbm], 2); spinf(&g_flagW[0], 1); }
    __syncthreads();
    load_chunk(sb, 0, tid, m0, n0);
    asm volatile("cp.async.commit_group;" ::: "memory");
    load_chunk(sb, 1, tid, m0, n0);
    asm volatile("cp.async.commit_group;" ::: "memory");

    for (int g = 0; g < NCHUNK; g++) {
        asm volatile("cp.async.wait_group 1;" ::: "memory");
        __syncthreads();
        uint32_t stA = sb + (uint32_t)(g % 3) * STG_B;
        uint32_t stB = stA + 16384u;
        {
            uint32_t ko = kbase;
            ldsm4(afr[0][0], stA + swz(rowA0 + ko));
            ldsm4(afr[0][1], stA + swz(rowA0 + 2048 + ko));
            ldsm4(bfr[0][0], stB + swz(rowB0 + ko));
            ldsm4(bfr[0][1], stB + swz(rowB0 + 2048 + ko));
            ldsm4(bfr[0][2], stB + swz(rowB0 + 4096 + ko));
            ldsm4(bfr[0][3], stB + swz(rowB0 + 6144 + ko));
        }
#pragma unroll
        for (int ks = 0; ks < 4; ks++) {
            int cur = ks & 1, nxt = cur ^ 1;
#pragma unroll
            for (int ni = 0; ni < 8; ni++)
                mma16816(acc[0][ni], afr[cur][0], bfr[cur][ni >> 1][ni & 1], bfr[cur][ni >> 1][(ni & 1) + 2]);
            if (ks < 3) {
                uint32_t ko = kbase + (uint32_t)(ks + 1) * 32;
                ldsm4(afr[nxt][0], stA + swz(rowA0 + ko));
                ldsm4(afr[nxt][1], stA + swz(rowA0 + 2048 + ko));
                ldsm4(bfr[nxt][0], stB + swz(rowB0 + ko));
                ldsm4(bfr[nxt][1], stB + swz(rowB0 + 2048 + ko));
                ldsm4(bfr[nxt][2], stB + swz(rowB0 + 4096 + ko));
                ldsm4(bfr[nxt][3], stB + swz(rowB0 + 6144 + ko));
            }
#pragma unroll
            for (int ni = 0; ni < 8; ni++)
                mma16816(acc[1][ni], afr[cur][1], bfr[cur][ni >> 1][ni & 1], bfr[cur][ni >> 1][(ni & 1) + 2]);
        }
        int gn = g + 2;
        if (gn < NCHUNK && (gn & 15) == 0) {      // entering a new term: gate its data
            if (tid == 0) { spinf(&g_flagA[(gn >> 4) * 64 + rbm], 2); spinf(&g_flagW[gn >> 4], 1); }
            __syncthreads();
        }
        if (gn < NCHUNK) load_chunk(sb, gn, tid, m0, n0);
        asm volatile("cp.async.commit_group;" ::: "memory");

        if ((g & 15) == 15) {   // term boundary: round term, bf16-add into global chain
            int t = g >> 4;
            if (g == 15) { if (tid == 0) spinf(&g_flagB, 1); __syncthreads(); }
            int rb2 = m0 + mw * 32 + (lane >> 2);
            int cb = n0 + nw * 64 + (lane & 3) * 2;
            uint32_t* chain0 = reinterpret_cast<uint32_t*>(g_O + (size_t)rb2 * NF + cb);
            uint32_t* chain1 = reinterpret_cast<uint32_t*>(g_O + (size_t)(rb2 + 8) * NF + cb);
            const uint32_t* bp = reinterpret_cast<const uint32_t*>(g_bias) + (cb >> 1);
#pragma unroll
            for (int mi = 0; mi < 2; mi++)
#pragma unroll
                for (int ni = 0; ni < 8; ni++) {
                    uint32_t lo = cvt2(acc[mi][ni][1], acc[mi][ni][0]);
                    uint32_t hi = cvt2(acc[mi][ni][3], acc[mi][ni][2]);
                    int off = mi * 16 * (NF / 2) + ni * 4;
                    if (t == 0) {
                        uint32_t bv = bp[ni * 4];
                        chain0[off] = badd2(lo, bv);
                        chain1[off] = badd2(hi, bv);
                    } else {
                        chain0[off] = badd2(chain0[off], lo);
                        chain1[off] = badd2(chain1[off], hi);
                    }
#pragma unroll
                    for (int r = 0; r < 4; r++) acc[mi][ni][r] = 0.0f;
                }
        }
    }
}

// ---- RMSNorm (bf16 in, fp32 math/out) ----
__global__ __launch_bounds__(256) void kan_rms(const float* __restrict__ scale, float* __restrict__ out) {
    int row = blockIdx.x, tid = threadIdx.x;
    uint2 d = *reinterpret_cast<const uint2*>(g_O + (size_t)row * NF + tid * 4);
    float v0 = __uint_as_float(d.x << 16), v1 = __uint_as_float(d.x & 0xFFFF0000u);
    float v2 = __uint_as_float(d.y << 16), v3 = __uint_as_float(d.y & 0xFFFF0000u);
    float ss = v0 * v0 + v1 * v1 + v2 * v2 + v3 * v3;
#pragma unroll
    for (int o = 16; o; o >>= 1) ss += __shfl_xor_sync(0xFFFFFFFFu, ss, o);
    __shared__ float red[8];
    if ((tid & 31) == 0) red[tid >> 5] = ss;
    __syncthreads();
    float tot = red[0] + red[1] + red[2] + red[3] + red[4] + red[5] + red[6] + red[7];
    float inv = rsqrtf(tot * (1.0f / 1024.0f) + 1e-6f);
    float4 o4;
    o4.x = v0 * inv * scale[tid * 4 + 0];
    o4.y = v1 * inv * scale[tid * 4 + 1];
    o4.z = v2 * inv * scale[tid * 4 + 2];
    o4.w = v3 * inv * scale[tid * 4 + 3];
    *reinterpret_cast<float4*>(out + (size_t)row * NF + tid * 4) = o4;
}

extern "C" void kernel_launch(void* const* d_in, const int* in_sizes, int n_in,
                              void* d_out, int out_size) {
    const float *x = nullptr, *bw = nullptr, *pw = nullptr, *sc = nullptr;
    for (int i = 0; i < n_in; i++) {
        if (in_sizes[i] == 8388608)       x  = (const float*)d_in[i];
        else if (in_sizes[i] == 1048576)  bw = (const float*)d_in[i];
        else if (in_sizes[i] == 13631488) pw = (const float*)d_in[i];
        else if (in_sizes[i] == 1024)     sc = (const float*)d_in[i];
    }
    cudaFuncSetAttribute(kan_gemm, cudaFuncAttributeMaxDynamicSharedMemorySize, SMEM_SZ);
    kan_zero<<<1, 256>>>();
    kan_gemm<<<NBUILD + NGEMM, 256, SMEM_SZ>>>(x, bw, pw);
    kan_rms<<<BROWS, 256>>>(sc, (float*)d_out);
}

// round 14
// speedup vs baseline: 1.9262x; 1.9262x over previous
#include <cuda_runtime.h>
#include <cuda_bf16.h>
#include <cstdint>

#define BROWS 8192
#define NF 1024
#define KTOT 13312              // 13 terms x 1024 along fused K axis

__device__ __align__(256) __nv_bfloat16 g_A[(size_t)BROWS * KTOT];  // [row][t*1024+k]
__device__ __align__(256) __nv_bfloat16 g_W[(size_t)NF * KTOT];     // [n][t*1024+k]
__device__ __align__(256) __nv_bfloat16 g_O[(size_t)BROWS * NF];    // bf16 chain / pre-RMS out
__device__ __align__(256) __nv_bfloat16 g_bias[NF];

__device__ __forceinline__ uint32_t smem_u32(const void* p) {
    uint32_t a;
    asm("{ .reg .u64 t; cvta.to.shared.u64 t, %1; cvt.u32.u64 %0, t; }" : "=r"(a) : "l"(p));
    return a;
}
__device__ __forceinline__ void cp16(uint32_t d, const void* s) {
    asm volatile("cp.async.cg.shared.global [%0], [%1], 16;" :: "r"(d), "l"(s) : "memory");
}
__device__ __forceinline__ void ldsm4(uint32_t* r, uint32_t a) {
    asm volatile("ldmatrix.sync.aligned.m8n8.x4.shared.b16 {%0,%1,%2,%3}, [%4];"
        : "=r"(r[0]), "=r"(r[1]), "=r"(r[2]), "=r"(r[3]) : "r"(a));
}
__device__ __forceinline__ void mma16816(float* c, const uint32_t* a, uint32_t b0, uint32_t b1) {
    asm volatile("mma.sync.aligned.m16n8k16.row.col.f32.bf16.bf16.f32 "
        "{%0,%1,%2,%3}, {%4,%5,%6,%7}, {%8,%9}, {%0,%1,%2,%3};"
        : "+f"(c[0]), "+f"(c[1]), "+f"(c[2]), "+f"(c[3])
        : "r"(a[0]), "r"(a[1]), "r"(a[2]), "r"(a[3]), "r"(b0), "r"(b1));
}
__device__ __forceinline__ uint32_t cvt2(float hi, float lo) {
    uint32_t d; asm("cvt.rn.bf16x2.f32 %0, %1, %2;" : "=r"(d) : "f"(hi), "f"(lo)); return d;
}
__device__ __forceinline__ uint32_t badd2(uint32_t a, uint32_t b) {
    uint32_t d; asm("add.rn.bf16x2 %0, %1, %2;" : "=r"(d) : "r"(a), "r"(b)); return d;
}
__device__ __forceinline__ uint32_t swz(uint32_t off) { return off ^ ((off >> 3) & 0x70); }

// ---- kernel 1: activations, 8 columns/thread, 16B stores per term ----
__global__ __launch_bounds__(256) void kan_build_A(const float* __restrict__ x) {
    size_t u = (size_t)blockIdx.x * 256 + threadIdx.x;   // 1M threads
    size_t r = u >> 7, grp = u & 127;                    // row, 8-col group
    const float4* xp = reinterpret_cast<const float4*>(x + r * NF + grp * 8);
    float4 a4 = xp[0], b4 = xp[1];
    float xv[8] = {a4.x, a4.y, a4.z, a4.w, b4.x, b4.y, b4.z, b4.w};
    __nv_bfloat16* row = g_A + r * KTOT + grp * 8;

    float a0[8], xs[8], Tp[8], Tc[8];
#pragma unroll
    for (int e = 0; e < 8; e++) {
        // silu: xb = bf16(x); e = bf16(exp(-xb)); d = bf16(1+e); s = bf16(1/d); a = bf16(xb*s)
        float xf = __bfloat162float(__float2bfloat16(xv[e]));
        float ee = __bfloat162float(__float2bfloat16(expf(-xf)));
        float dd = __bfloat162float(__float2bfloat16(1.0f + ee));
        float s  = __bfloat162float(__float2bfloat16(1.0f / dd));
        a0[e] = xf * s;
        xs[e] = tanhf(xv[e]);
        Tp[e] = 1.0f; Tc[e] = xs[e];
    }
    *reinterpret_cast<uint4*>(row) =
        make_uint4(cvt2(a0[1], a0[0]), cvt2(a0[3], a0[2]), cvt2(a0[5], a0[4]), cvt2(a0[7], a0[6]));
    *reinterpret_cast<uint4*>(row + 1024) =
        make_uint4(cvt2(xs[1], xs[0]), cvt2(xs[3], xs[2]), cvt2(xs[5], xs[4]), cvt2(xs[7], xs[6]));
#pragma unroll
    for (int k = 2; k <= 12; k++) {
        float Tn[8];
#pragma unroll
        for (int e = 0; e < 8; e++) {
            Tn[e] = 2.0f * xs[e] * Tc[e] - Tp[e];
            Tp[e] = Tc[e]; Tc[e] = Tn[e];
        }
        *reinterpret_cast<uint4*>(row + (size_t)k * 1024) =
            make_uint4(cvt2(Tn[1], Tn[0]), cvt2(Tn[3], Tn[2]), cvt2(Tn[5], Tn[4]), cvt2(Tn[7], Tn[6]));
    }
}

// ---- kernel 2: W transpose [k][n] f32 -> [n][t*1024+k] bf16 ----
__global__ __launch_bounds__(256) void kan_prep_W(const float* __restrict__ base, const float* __restrict__ poly) {
    __shared__ float tile[32][33];
    int t = blockIdx.z;
    const float* src = (t == 0) ? base : (poly + (size_t)t * NF * NF);
    int n0 = blockIdx.x * 32, k0 = blockIdx.y * 32, tx = threadIdx.x, ty = threadIdx.y;
#pragma unroll
    for (int i = 0; i < 4; i++)
        tile[ty + i * 8][tx] = src[(size_t)(k0 + ty + i * 8) * NF + n0 + tx];
    __syncthreads();
#pragma unroll
    for (int i = 0; i < 4; i++)
        g_W[(size_t)(n0 + ty + i * 8) * KTOT + t * 1024 + k0 + tx] = __float2bfloat16(tile[tx][ty + i * 8]);
}

// ---- kernel 3: bias = bf16( fp32 colsum of bf16(pw[0]) ) ----
__global__ __launch_bounds__(256) void kan_bias(const float* __restrict__ poly) {
    int n = blockIdx.x * 256 + threadIdx.x;
    float a = 0.0f;
    for (int k = 0; k < NF; k++)
        a += __bfloat162float(__float2bfloat16(poly[(size_t)k * NF + n]));
    g_bias[n] = __float2bfloat16(a);
}

// ---- kernel 4: 128x128-tile GEMM, 2 CTAs/SM, ks-level fragment pipelining ----
#define STG_B 32768u            // A 128x64 (16KB) + W 128x64 (16KB)
#define SMEM_SZ (3 * 32768)
#define NCHUNK 208              // 13312/64; term t = chunk>>4

__device__ __forceinline__ void load_chunk(uint32_t sb, int g, int tid, int m0, int n0) {
    uint32_t stg = sb + (uint32_t)(g % 3) * STG_B;
    const __nv_bfloat16* Ab = g_A + (size_t)m0 * KTOT + g * 64;
    const __nv_bfloat16* Wb = g_W + (size_t)n0 * KTOT + g * 64;
#pragma unroll
    for (int k = 0; k < 8; k++) {
        int i = tid + k * 256;
        int half_ = i >> 10, j = i & 1023, r = j >> 3, s = j & 7;
        const __nv_bfloat16* src = (half_ ? Wb : Ab) + (size_t)r * KTOT + s * 8;
        cp16(stg + (half_ ? 16384u : 0u) + swz((uint32_t)(r * 128 + s * 16)), src);
    }
}

__global__ __launch_bounds__(256, 2) void kan_gemm() {
    extern __shared__ char smem[];
    uint32_t sb = smem_u32(smem);
    int tid = threadIdx.x, wid = tid >> 5, lane = tid & 31;
    int m0 = (blockIdx.x >> 3) * 128, n0 = (blockIdx.x & 7) * 128;
    int mw = wid >> 1, nw = wid & 1;          // 4x2 warp grid, warp tile 32x64
    uint32_t rowA0 = (uint32_t)((mw * 32 + (lane & 15)) * 128);
    uint32_t rowB0 = (uint32_t)((nw * 64 + (lane & 15)) * 128);
    uint32_t kbase = (uint32_t)((lane >> 4) * 16);

    float acc[2][8][4];
#pragma unroll
    for (int a = 0; a < 2; a++)
#pragma unroll
        for (int b = 0; b < 8; b++)
#pragma unroll
            for (int r = 0; r < 4; r++) acc[a][b][r] = 0.0f;

    uint32_t afr[2][2][4];     // [buf][mi][frag]
    uint32_t bfr[2][4][4];     // [buf][nh][frag]

    load_chunk(sb, 0, tid, m0, n0);
    asm volatile("cp.async.commit_group;" ::: "memory");
    load_chunk(sb, 1, tid, m0, n0);
    asm volatile("cp.async.commit_group;" ::: "memory");

    for (int g = 0; g < NCHUNK; g++) {
        asm volatile("cp.async.wait_group 1;" ::: "memory");
        __syncthreads();
        uint32_t stA = sb + (uint32_t)(g % 3) * STG_B;
        uint32_t stB = stA + 16384u;
        {
            uint32_t ko = kbase;
            ldsm4(afr[0][0], stA + swz(rowA0 + ko));
            ldsm4(afr[0][1], stA + swz(rowA0 + 2048 + ko));
            ldsm4(bfr[0][0], stB + swz(rowB0 + ko));
            ldsm4(bfr[0][1], stB + swz(rowB0 + 2048 + ko));
            ldsm4(bfr[0][2], stB + swz(rowB0 + 4096 + ko));
            ldsm4(bfr[0][3], stB + swz(rowB0 + 6144 + ko));
        }
#pragma unroll
        for (int ks = 0; ks < 4; ks++) {
            int cur = ks & 1, nxt = cur ^ 1;
#pragma unroll
            for (int ni = 0; ni < 8; ni++)
                mma16816(acc[0][ni], afr[cur][0], bfr[cur][ni >> 1][ni & 1], bfr[cur][ni >> 1][(ni & 1) + 2]);
            if (ks < 3) {
                uint32_t ko = kbase + (uint32_t)(ks + 1) * 32;
                ldsm4(afr[nxt][0], stA + swz(rowA0 + ko));
                ldsm4(afr[nxt][1], stA + swz(rowA0 + 2048 + ko));
                ldsm4(bfr[nxt][0], stB + swz(rowB0 + ko));
                ldsm4(bfr[nxt][1], stB + swz(rowB0 + 2048 + ko));
                ldsm4(bfr[nxt][2], stB + swz(rowB0 + 4096 + ko));
                ldsm4(bfr[nxt][3], stB + swz(rowB0 + 6144 + ko));
            }
#pragma unroll
            for (int ni = 0; ni < 8; ni++)
                mma16816(acc[1][ni], afr[cur][1], bfr[cur][ni >> 1][ni & 1], bfr[cur][ni >> 1][(ni & 1) + 2]);
        }
        if (g + 2 < NCHUNK) load_chunk(sb, g + 2, tid, m0, n0);
        asm volatile("cp.async.commit_group;" ::: "memory");

        if ((g & 15) == 15) {   // term boundary: round term, bf16-add into global chain
            int t = g >> 4;
            int rb = m0 + mw * 32 + (lane >> 2);
            int cb = n0 + nw * 64 + (lane & 3) * 2;
            uint32_t* chain0 = reinterpret_cast<uint32_t*>(g_O + (size_t)rb * NF + cb);
            uint32_t* chain1 = reinterpret_cast<uint32_t*>(g_O + (size_t)(rb + 8) * NF + cb);
            const uint32_t* bp = reinterpret_cast<const uint32_t*>(g_bias) + (cb >> 1);
#pragma unroll
            for (int mi = 0; mi < 2; mi++)
#pragma unroll
                for (int ni = 0; ni < 8; ni++) {
                    uint32_t lo = cvt2(acc[mi][ni][1], acc[mi][ni][0]);
                    uint32_t hi = cvt2(acc[mi][ni][3], acc[mi][ni][2]);
                    int off = mi * 16 * (NF / 2) + ni * 4;   // u32 units
                    if (t == 0) {
                        uint32_t bv = bp[ni * 4];
                        chain0[off] = badd2(lo, bv);
                        chain1[off] = badd2(hi, bv);
                    } else {
                        chain0[off] = badd2(chain0[off], lo);
                        chain1[off] = badd2(chain1[off], hi);
                    }
#pragma unroll
                    for (int r = 0; r < 4; r++) acc[mi][ni][r] = 0.0f;
                }
        }
    }
}

// ---- kernel 5: RMSNorm (bf16 in, fp32 math/out) ----
__global__ __launch_bounds__(256) void kan_rms(const float* __restrict__ scale, float* __restrict__ out) {
    int row = blockIdx.x, tid = threadIdx.x;
    uint2 d = *reinterpret_cast<const uint2*>(g_O + (size_t)row * NF + tid * 4);
    float v0 = __uint_as_float(d.x << 16), v1 = __uint_as_float(d.x & 0xFFFF0000u);
    float v2 = __uint_as_float(d.y << 16), v3 = __uint_as_float(d.y & 0xFFFF0000u);
    float ss = v0 * v0 + v1 * v1 + v2 * v2 + v3 * v3;
#pragma unroll
    for (int o = 16; o; o >>= 1) ss += __shfl_xor_sync(0xFFFFFFFFu, ss, o);
    __shared__ float red[8];
    if ((tid & 31) == 0) red[tid >> 5] = ss;
    __syncthreads();
    float tot = red[0] + red[1] + red[2] + red[3] + red[4] + red[5] + red[6] + red[7];
    float inv = rsqrtf(tot * (1.0f / 1024.0f) + 1e-6f);
    float4 o4;
    o4.x = v0 * inv * scale[tid * 4 + 0];
    o4.y = v1 * inv * scale[tid * 4 + 1];
    o4.z = v2 * inv * scale[tid * 4 + 2];
    o4.w = v3 * inv * scale[tid * 4 + 3];
    *reinterpret_cast<float4*>(out + (size_t)row * NF + tid * 4) = o4;
}

extern "C" void kernel_launch(void* const* d_in, const int* in_sizes, int n_in,
                              void* d_out, int out_size) {
    const float *x = nullptr, *bw = nullptr, *pw = nullptr, *sc = nullptr;
    for (int i = 0; i < n_in; i++) {
        if (in_sizes[i] == 8388608)       x  = (const float*)d_in[i];
        else if (in_sizes[i] == 1048576)  bw = (const float*)d_in[i];
        else if (in_sizes[i] == 13631488) pw = (const float*)d_in[i];
        else if (in_sizes[i] == 1024)     sc = (const float*)d_in[i];
    }
    cudaFuncSetAttribute(kan_gemm, cudaFuncAttributeMaxDynamicSharedMemorySize, SMEM_SZ);
    kan_build_A<<<BROWS * NF / 8 / 256, 256>>>(x);
    kan_prep_W<<<dim3(32, 32, 13), dim3(32, 8)>>>(bw, pw);
    kan_bias<<<4, 256>>>(pw);
    kan_gemm<<<512, 256, SMEM_SZ>>>();
    kan_rms<<<BROWS, 256>>>(sc, (float*)d_out);
}

// round 15
// speedup vs baseline: 1.9447x; 1.0096x over previous
#include <cuda_runtime.h>
#include <cuda_bf16.h>
#include <cstdint>

#define BROWS 8192
#define NF 1024
#define KTOT 13312              // 13 terms x 1024 along fused K axis

#define PA 4096                 // build_A blocks
#define PW 13312                // prep_W blocks (13 x 32 x 32)
#define PB 4                    // bias blocks
#define NPREP (PA + PW + PB)

__device__ __align__(256) __nv_bfloat16 g_A[(size_t)BROWS * KTOT];  // [row][t*1024+k]
__device__ __align__(256) __nv_bfloat16 g_W[(size_t)NF * KTOT];     // [n][t*1024+k]
__device__ __align__(256) __nv_bfloat16 g_O[(size_t)BROWS * NF];    // bf16 chain / pre-RMS out
__device__ __align__(256) __nv_bfloat16 g_bias[NF];

__device__ __forceinline__ uint32_t smem_u32(const void* p) {
    uint32_t a;
    asm("{ .reg .u64 t; cvta.to.shared.u64 t, %1; cvt.u32.u64 %0, t; }" : "=r"(a) : "l"(p));
    return a;
}
__device__ __forceinline__ void cp16(uint32_t d, const void* s) {
    asm volatile("cp.async.cg.shared.global [%0], [%1], 16;" :: "r"(d), "l"(s) : "memory");
}
__device__ __forceinline__ void ldsm4(uint32_t* r, uint32_t a) {
    asm volatile("ldmatrix.sync.aligned.m8n8.x4.shared.b16 {%0,%1,%2,%3}, [%4];"
        : "=r"(r[0]), "=r"(r[1]), "=r"(r[2]), "=r"(r[3]) : "r"(a));
}
__device__ __forceinline__ void mma16816(float* c, const uint32_t* a, uint32_t b0, uint32_t b1) {
    asm volatile("mma.sync.aligned.m16n8k16.row.col.f32.bf16.bf16.f32 "
        "{%0,%1,%2,%3}, {%4,%5,%6,%7}, {%8,%9}, {%0,%1,%2,%3};"
        : "+f"(c[0]), "+f"(c[1]), "+f"(c[2]), "+f"(c[3])
        : "r"(a[0]), "r"(a[1]), "r"(a[2]), "r"(a[3]), "r"(b0), "r"(b1));
}
__device__ __forceinline__ uint32_t cvt2(float hi, float lo) {
    uint32_t d; asm("cvt.rn.bf16x2.f32 %0, %1, %2;" : "=r"(d) : "f"(hi), "f"(lo)); return d;
}
__device__ __forceinline__ uint32_t badd2(uint32_t a, uint32_t b) {
    uint32_t d; asm("add.rn.bf16x2 %0, %1, %2;" : "=r"(d) : "r"(a), "r"(b)); return d;
}
__device__ __forceinline__ uint32_t swz(uint32_t off) { return off ^ ((off >> 3) & 0x70); }

// ---- kernel 1: fused prologue — three independent block regions ----
__global__ __launch_bounds__(256) void kan_prep(const float* __restrict__ x,
                                                const float* __restrict__ bw,
                                                const float* __restrict__ pw) {
    int bid = blockIdx.x, tid = threadIdx.x;
    if (bid < PA) {
        // ===== build_A: 8 columns/thread, 16B stores per term =====
        size_t u = (size_t)bid * 256 + tid;
        size_t r = u >> 7, grp = u & 127;
        const float4* xp = reinterpret_cast<const float4*>(x + r * NF + grp * 8);
        float4 a4 = xp[0], b4 = xp[1];
        float xv[8] = {a4.x, a4.y, a4.z, a4.w, b4.x, b4.y, b4.z, b4.w};
        __nv_bfloat16* row = g_A + r * KTOT + grp * 8;
        float a0[8], xs[8], Tp[8], Tc[8];
#pragma unroll
        for (int e = 0; e < 8; e++) {
            float xf = __bfloat162float(__float2bfloat16(xv[e]));
            float ee = __bfloat162float(__float2bfloat16(expf(-xf)));
            float dd = __bfloat162float(__float2bfloat16(1.0f + ee));
            float s  = __bfloat162float(__float2bfloat16(1.0f / dd));
            a0[e] = xf * s;
            xs[e] = tanhf(xv[e]);
            Tp[e] = 1.0f; Tc[e] = xs[e];
        }
        *reinterpret_cast<uint4*>(row) =
            make_uint4(cvt2(a0[1], a0[0]), cvt2(a0[3], a0[2]), cvt2(a0[5], a0[4]), cvt2(a0[7], a0[6]));
        *reinterpret_cast<uint4*>(row + 1024) =
            make_uint4(cvt2(xs[1], xs[0]), cvt2(xs[3], xs[2]), cvt2(xs[5], xs[4]), cvt2(xs[7], xs[6]));
#pragma unroll
        for (int k = 2; k <= 12; k++) {
            float Tn[8];
#pragma unroll
            for (int e = 0; e < 8; e++) {
                Tn[e] = 2.0f * xs[e] * Tc[e] - Tp[e];
                Tp[e] = Tc[e]; Tc[e] = Tn[e];
            }
            *reinterpret_cast<uint4*>(row + (size_t)k * 1024) =
                make_uint4(cvt2(Tn[1], Tn[0]), cvt2(Tn[3], Tn[2]), cvt2(Tn[5], Tn[4]), cvt2(Tn[7], Tn[6]));
        }
    } else if (bid < PA + PW) {
        // ===== prep_W: transpose one 32x32 tile of term t =====
        __shared__ float tile[32][33];
        int w = bid - PA;
        int t = w >> 10, rr = w & 1023;
        int n0 = (rr & 31) * 32, k0 = (rr >> 5) * 32;
        const float* src = (t == 0) ? bw : (pw + (size_t)t * NF * NF);
        int tx = tid & 31, ty = tid >> 5;   // 32 x 8
#pragma unroll
        for (int i = 0; i < 4; i++)
            tile[ty + i * 8][tx] = src[(size_t)(k0 + ty + i * 8) * NF + n0 + tx];
        __syncthreads();
#pragma unroll
        for (int i = 0; i < 4; i++)
            g_W[(size_t)(n0 + ty + i * 8) * KTOT + t * 1024 + k0 + tx] = __float2bfloat16(tile[tx][ty + i * 8]);
    } else {
        // ===== bias: bf16( f32 colsum of bf16(pw[0]) ) =====
        int n = (bid - PA - PW) * 256 + tid;
        float a = 0.0f;
        for (int k = 0; k < NF; k++)
            a += __bfloat162float(__float2bfloat16(pw[(size_t)k * NF + n]));
        g_bias[n] = __float2bfloat16(a);
    }
}

// ---- kernel 2: 128x128-tile GEMM, 2 CTAs/SM, ks-level fragment pipelining ----
#define STG_B 32768u            // A 128x64 (16KB) + W 128x64 (16KB)
#define SMEM_SZ (3 * 32768)
#define NCHUNK 208              // 13312/64; term t = chunk>>4

__device__ __forceinline__ void load_chunk(uint32_t sb, int g, int tid, int m0, int n0) {
    uint32_t stg = sb + (uint32_t)(g % 3) * STG_B;
    const __nv_bfloat16* Ab = g_A + (size_t)m0 * KTOT + g * 64;
    const __nv_bfloat16* Wb = g_W + (size_t)n0 * KTOT + g * 64;
#pragma unroll
    for (int k = 0; k < 8; k++) {
        int i = tid + k * 256;
        int half_ = i >> 10, j = i & 1023, r = j >> 3, s = j & 7;
        const __nv_bfloat16* src = (half_ ? Wb : Ab) + (size_t)r * KTOT + s * 8;
        cp16(stg + (half_ ? 16384u : 0u) + swz((uint32_t)(r * 128 + s * 16)), src);
    }
}

__global__ __launch_bounds__(256, 2) void kan_gemm() {
    extern __shared__ char smem[];
    uint32_t sb = smem_u32(smem);
    int tid = threadIdx.x, wid = tid >> 5, lane = tid & 31;
    int m0 = (blockIdx.x >> 3) * 128, n0 = (blockIdx.x & 7) * 128;
    int mw = wid >> 1, nw = wid & 1;          // 4x2 warp grid, warp tile 32x64
    uint32_t rowA0 = (uint32_t)((mw * 32 + (lane & 15)) * 128);
    uint32_t rowB0 = (uint32_t)((nw * 64 + (lane & 15)) * 128);
    uint32_t kbase = (uint32_t)((lane >> 4) * 16);

    float acc[2][8][4];
#pragma unroll
    for (int a = 0; a < 2; a++)
#pragma unroll
        for (int b = 0; b < 8; b++)
#pragma unroll
            for (int r = 0; r < 4; r++) acc[a][b][r] = 0.0f;

    uint32_t afr[2][2][4];
    uint32_t bfr[2][4][4];

    load_chunk(sb, 0, tid, m0, n0);
    asm volatile("cp.async.commit_group;" ::: "memory");
    load_chunk(sb, 1, tid, m0, n0);
    asm volatile("cp.async.commit_group;" ::: "memory");

    for (int g = 0; g < NCHUNK; g++) {
        asm volatile("cp.async.wait_group 1;" ::: "memory");
        __syncthreads();
        uint32_t stA = sb + (uint32_t)(g % 3) * STG_B;
        uint32_t stB = stA + 16384u;
        {
            uint32_t ko = kbase;
            ldsm4(afr[0][0], stA + swz(rowA0 + ko));
            ldsm4(afr[0][1], stA + swz(rowA0 + 2048 + ko));
            ldsm4(bfr[0][0], stB + swz(rowB0 + ko));
            ldsm4(bfr[0][1], stB + swz(rowB0 + 2048 + ko));
            ldsm4(bfr[0][2], stB + swz(rowB0 + 4096 + ko));
            ldsm4(bfr[0][3], stB + swz(rowB0 + 6144 + ko));
        }
#pragma unroll
        for (int ks = 0; ks < 4; ks++) {
            int cur = ks & 1, nxt = cur ^ 1;
#pragma unroll
            for (int ni = 0; ni < 8; ni++)
                mma16816(acc[0][ni], afr[cur][0], bfr[cur][ni >> 1][ni & 1], bfr[cur][ni >> 1][(ni & 1) + 2]);
            if (ks < 3) {
                uint32_t ko = kbase + (uint32_t)(ks + 1) * 32;
                ldsm4(afr[nxt][0], stA + swz(rowA0 + ko));
                ldsm4(afr[nxt][1], stA + swz(rowA0 + 2048 + ko));
                ldsm4(bfr[nxt][0], stB + swz(rowB0 + ko));
                ldsm4(bfr[nxt][1], stB + swz(rowB0 + 2048 + ko));
                ldsm4(bfr[nxt][2], stB + swz(rowB0 + 4096 + ko));
                ldsm4(bfr[nxt][3], stB + swz(rowB0 + 6144 + ko));
            }
#pragma unroll
            for (int ni = 0; ni < 8; ni++)
                mma16816(acc[1][ni], afr[cur][1], bfr[cur][ni >> 1][ni & 1], bfr[cur][ni >> 1][(ni & 1) + 2]);
        }
        if (g + 2 < NCHUNK) load_chunk(sb, g + 2, tid, m0, n0);
        asm volatile("cp.async.commit_group;" ::: "memory");

        if ((g & 15) == 15) {   // term boundary: round term, bf16-add into global chain
            int t = g >> 4;
            int rb = m0 + mw * 32 + (lane >> 2);
            int cb = n0 + nw * 64 + (lane & 3) * 2;
            uint32_t* chain0 = reinterpret_cast<uint32_t*>(g_O + (size_t)rb * NF + cb);
            uint32_t* chain1 = reinterpret_cast<uint32_t*>(g_O + (size_t)(rb + 8) * NF + cb);
            const uint32_t* bp = reinterpret_cast<const uint32_t*>(g_bias) + (cb >> 1);
#pragma unroll
            for (int mi = 0; mi < 2; mi++)
#pragma unroll
                for (int ni = 0; ni < 8; ni++) {
                    uint32_t lo = cvt2(acc[mi][ni][1], acc[mi][ni][0]);
                    uint32_t hi = cvt2(acc[mi][ni][3], acc[mi][ni][2]);
                    int off = mi * 16 * (NF / 2) + ni * 4;
                    if (t == 0) {
                        uint32_t bv = bp[ni * 4];
                        chain0[off] = badd2(lo, bv);
                        chain1[off] = badd2(hi, bv);
                    } else {
                        chain0[off] = badd2(chain0[off], lo);
                        chain1[off] = badd2(chain1[off], hi);
                    }
#pragma unroll
                    for (int r = 0; r < 4; r++) acc[mi][ni][r] = 0.0f;
                }
        }
    }
}

// ---- kernel 3: RMSNorm (bf16 in, fp32 math/out) ----
__global__ __launch_bounds__(256) void kan_rms(const float* __restrict__ scale, float* __restrict__ out) {
    int row = blockIdx.x, tid = threadIdx.x;
    uint2 d = *reinterpret_cast<const uint2*>(g_O + (size_t)row * NF + tid * 4);
    float v0 = __uint_as_float(d.x << 16), v1 = __uint_as_float(d.x & 0xFFFF0000u);
    float v2 = __uint_as_float(d.y << 16), v3 = __uint_as_float(d.y & 0xFFFF0000u);
    float ss = v0 * v0 + v1 * v1 + v2 * v2 + v3 * v3;
#pragma unroll
    for (int o = 16; o; o >>= 1) ss += __shfl_xor_sync(0xFFFFFFFFu, ss, o);
    __shared__ float red[8];
    if ((tid & 31) == 0) red[tid >> 5] = ss;
    __syncthreads();
    float tot = red[0] + red[1] + red[2] + red[3] + red[4] + red[5] + red[6] + red[7];
    float inv = rsqrtf(tot * (1.0f / 1024.0f) + 1e-6f);
    float4 o4;
    o4.x = v0 * inv * scale[tid * 4 + 0];
    o4.y = v1 * inv * scale[tid * 4 + 1];
    o4.z = v2 * inv * scale[tid * 4 + 2];
    o4.w = v3 * inv * scale[tid * 4 + 3];
    *reinterpret_cast<float4*>(out + (size_t)row * NF + tid * 4) = o4;
}

extern "C" void kernel_launch(void* const* d_in, const int* in_sizes, int n_in,
                              void* d_out, int out_size) {
    const float *x = nullptr, *bw = nullptr, *pw = nullptr, *sc = nullptr;
    for (int i = 0; i < n_in; i++) {
        if (in_sizes[i] == 8388608)       x  = (const float*)d_in[i];
        else if (in_sizes[i] == 1048576)  bw = (const float*)d_in[i];
        else if (in_sizes[i] == 13631488) pw = (const float*)d_in[i];
        else if (in_sizes[i] == 1024)     sc = (const float*)d_in[i];
    }
    cudaFuncSetAttribute(kan_gemm, cudaFuncAttributeMaxDynamicSharedMemorySize, SMEM_SZ);
    kan_prep<<<NPREP, 256>>>(x, bw, pw);
    kan_gemm<<<512, 256, SMEM_SZ>>>();
    kan_rms<<<BROWS, 256>>>(sc, (float*)d_out);
}